// round 6
// baseline (speedup 1.0000x reference)
#include <cuda_runtime.h>
#include <cuda_bf16.h>

typedef unsigned long long ull;

#define KD 64      // feature dimension
#define LD 8192    // leading dim of transposed feature matrix
#define MB 64      // goals per block (8 warps x 8 goals)
#define NB 256     // features per tile (lane owns 4 + 4)
#define NSPLIT 8   // feature-dim split per step
#define NPTS 8192

// ---------------- scratch (__device__ globals; no allocation) ----------------
__device__ float g_FT[KD * LD];          // transposed features [64][8192]
__device__ float g_norms[LD];            // |f|^2
__device__ unsigned g_candU[4096 * NSPLIT * 3];
__device__ int      g_candI[4096 * NSPLIT * 3];
__device__ ull g_kA[NPTS], g_kB[NPTS];   // round-1/2 sort keys (bits<<32|pos)
__device__ int g_rA[NPTS], g_rB[NPTS];   // ranks
__device__ int g_perm[NPTS];             // final permutation (rand_inds = first 4096)

// ---------------- threefry2x32 (exact JAX) ----------------
__device__ __forceinline__ void tf2x32(unsigned k0, unsigned k1,
                                       unsigned c0, unsigned c1,
                                       unsigned &o0, unsigned &o1) {
    unsigned ks2 = k0 ^ k1 ^ 0x1BD11BDAu;
    unsigned x0 = c0 + k0, x1 = c1 + k1;
#define TF_RND(r) { x0 += x1; x1 = (x1 << (r)) | (x1 >> (32 - (r))); x1 ^= x0; }
    TF_RND(13) TF_RND(15) TF_RND(26) TF_RND(6)   x0 += k1;  x1 += ks2 + 1u;
    TF_RND(17) TF_RND(29) TF_RND(16) TF_RND(24)  x0 += ks2; x1 += k0 + 2u;
    TF_RND(13) TF_RND(15) TF_RND(26) TF_RND(6)   x0 += k0;  x1 += k1 + 3u;
    TF_RND(17) TF_RND(29) TF_RND(16) TF_RND(24)  x0 += k1;  x1 += ks2 + 4u;
    TF_RND(13) TF_RND(15) TF_RND(26) TF_RND(6)   x0 += ks2; x1 += k0 + 5u;
#undef TF_RND
    o0 = x0; o1 = x1;
}

// partitionable threefry: round r: key,subkey = split(key), counters (0,0),(0,1)
__device__ __forceinline__ void subkeys(unsigned &s10, unsigned &s11,
                                        unsigned &s20, unsigned &s21) {
    unsigned n0, n1;
    tf2x32(0u, 42u, 0u, 0u, n0, n1);
    tf2x32(0u, 42u, 0u, 1u, s10, s11);
    tf2x32(n0, n1, 0u, 1u, s20, s21);
}

// bits[i] = y0 ^ y1 with counter (0, i); stable-sort key = (bits<<32) | i.
// Also zeroes the rank arrays (graph replays must be deterministic).
__global__ void keys_k() {
    int i = blockIdx.x * blockDim.x + threadIdx.x;
    if (i >= NPTS) return;
    unsigned s10, s11, s20, s21;
    subkeys(s10, s11, s20, s21);
    unsigned lo, hi;
    tf2x32(s10, s11, 0u, (unsigned)i, lo, hi);
    g_kA[i] = ((ull)(lo ^ hi) << 32) | (unsigned)i;
    tf2x32(s20, s21, 0u, (unsigned)i, lo, hi);
    g_kB[i] = ((ull)(lo ^ hi) << 32) | (unsigned)i;
    g_rA[i] = 0; g_rB[i] = 0;
}

// rank[i] = #{j : key_j < key_i}, segmented over j, REDG-accumulated.
#define SEG 2048
__global__ __launch_bounds__(256) void rank_k() {
    __shared__ ull tile[SEG];
    const ull* K = blockIdx.y ? g_kB : g_kA;
    int* R = blockIdx.y ? g_rB : g_rA;
    int i = blockIdx.x * 256 + threadIdx.x;
    int base = blockIdx.z * SEG;
    ull my = K[i];
    for (int j = threadIdx.x; j < SEG; j += 256) tile[j] = K[base + j];
    __syncthreads();
    int cnt = 0;
#pragma unroll 8
    for (int j = 0; j < SEG; j++) cnt += (tile[j] < my);
    atomicAdd(&R[i], cnt);
}

// perm[rB[rA[i]]] = i
__global__ void compose_k() {
    int i = blockIdx.x * blockDim.x + threadIdx.x;
    if (i >= NPTS) return;
    g_perm[g_rB[g_rA[i]]] = i;
}

// ---------------- transpose rows[n][64] -> g_FT[64][foff+...] ----------------
__global__ void transpose_k(const float* __restrict__ in, int foff) {
    __shared__ float t[32][33];
    int f0 = blockIdx.x * 32, d0 = blockIdx.y * 32;
    int tx = threadIdx.x, ty = threadIdx.y;
    t[ty][tx] = in[(size_t)(f0 + ty) * KD + d0 + tx];
    __syncthreads();
    g_FT[(size_t)(d0 + ty) * LD + foff + f0 + tx] = t[tx][ty];
}

// ---------------- norms: |f|^2 for f in [foff, foff+n) ----------------
__global__ void norms_k(int foff) {
    int f = foff + blockIdx.x * blockDim.x + threadIdx.x;
    float s = 0.f;
#pragma unroll
    for (int k = 0; k < KD; k++) {
        float v = g_FT[(size_t)k * LD + f];
        s = __fadd_rn(s, __fmul_rn(v, v));
    }
    g_norms[f] = s;
}

// ---------------- ordered-float key for tie-break-by-lower-index min ----------------
__device__ __forceinline__ unsigned fkey(float f) {
    unsigned u = __float_as_uint(f);
    return (u & 0x80000000u) ? ~u : (u | 0x80000000u);
}

__device__ __forceinline__ void fma_x2(ull &acc, ull a, ull b) {
    asm("fma.rn.f32x2 %0, %1, %2, %3;" : "=l"(acc) : "l"(a), "l"(b), "l"(acc));
}
__device__ __forceinline__ ull add_x2(ull a, ull b) {
    ull r; asm("add.rn.f32x2 %0, %1, %2;" : "=l"(r) : "l"(a), "l"(b)); return r;
}
__device__ __forceinline__ ull fma_x2v(ull a, ull b, ull c) {
    ull r; asm("fma.rn.f32x2 %0, %1, %2, %3;" : "=l"(r) : "l"(a), "l"(b), "l"(c));
    return r;
}
__device__ __forceinline__ ull pack2(float lo, float hi) {
    ull r; asm("mov.b64 %0, {%1, %2};" : "=l"(r) : "f"(lo), "f"(hi)); return r;
}

__device__ __forceinline__ void top3_ins(float v, int idx, float* bv, int* bi) {
    if (v < bv[2]) {
        if (v < bv[1]) {
            bv[2] = bv[1]; bi[2] = bi[1];
            if (v < bv[0]) {
                bv[1] = bv[0]; bi[1] = bi[0];
                bv[0] = v; bi[0] = idx;
            } else { bv[1] = v; bi[1] = idx; }
        } else { bv[2] = v; bi[2] = idx; }
    }
}

// ---------------- KNN top-3: f32x2, 8 goals x 8 feats per lane, occ 2 ----------------
// grid = (4096/MB, NSPLIT), block = 256 (8 warps), 2 blocks/SM (16 warps).
// Warp w owns goals [w*8, w*8+8); lane owns feats {lane*4..+3} and {128+lane*4..+3}.
// Per SM-k @16 warps: fma 256 cyc (binding), crossbar 192 (25% slack), issue ~168.
__global__ __launch_bounds__(256, 2) void knn_k(int nfeat, int usePerm) {
    extern __shared__ float sm[];
    float* Fs = sm;                        // [64][256]   feats
    float* Gp = Fs + KD * NB;              // [64][64*2]  pair-duplicated goals
    float* Ns = Gp + KD * MB * 2;          // [256]
    float* Gn = Ns + NB;                   // [64]
    ulonglong2* FsV = (ulonglong2*)Fs;     // row k: 64 entries (16B = 4 feats)
    float4* Gp4 = (float4*)Gp;             // row k: 32 entries ({g,g,g',g'})
    ull* NsU = (ull*)Ns;

    int tid = threadIdx.x;
    int lane = tid & 31, w = tid >> 5;
    int g0 = blockIdx.x * MB;
    int part = nfeat / NSPLIT;
    int fBeg = blockIdx.y * part, fEnd = fBeg + part;

    for (int i = tid; i < KD * MB; i += 256) {
        int k = i >> 6, j = i & 63;
        int src = usePerm ? g_perm[g0 + j] : (g0 + j);
        float v = g_FT[(size_t)k * LD + src];
        ((float2*)Gp)[k * MB + j] = make_float2(v, v);
    }
    if (tid < MB) {
        int src = usePerm ? g_perm[g0 + tid] : (g0 + tid);
        Gn[tid] = g_norms[src];
    }

    float bv[8][3]; int bi[8][3];
#pragma unroll
    for (int r = 0; r < 8; r++)
#pragma unroll
        for (int t = 0; t < 3; t++) { bv[r][t] = 3.402823466e38f; bi[r][t] = 0; }

    const ull NEG2 = ((ull)0xC0000000u << 32) | 0xC0000000u;   // {-2.f, -2.f}

    for (int f0 = fBeg; f0 < fEnd; f0 += NB) {
        __syncthreads();
        for (int i = tid; i < KD * NB / 4; i += 256) {
            int k = i >> 6, c = i & 63;
            ((float4*)Fs)[k * 64 + c] =
                *reinterpret_cast<const float4*>(&g_FT[(size_t)k * LD + f0 + 4 * c]);
        }
        if (tid < NB) Ns[tid] = g_norms[f0 + tid];
        __syncthreads();

        ull acc[8][4];
#pragma unroll
        for (int r = 0; r < 8; r++)
#pragma unroll
            for (int p = 0; p < 4; p++) acc[r][p] = 0ull;

#pragma unroll 8
        for (int k = 0; k < KD; k++) {
            ulonglong2 fa = FsV[k * 64 + lane];        // feats lane*4 .. +3
            ulonglong2 fb = FsV[k * 64 + 32 + lane];   // feats 128+lane*4 .. +3
#pragma unroll
            for (int i = 0; i < 4; i++) {
                float4 gq = Gp4[k * 32 + w * 4 + i];   // {g2i,g2i, g2i+1,g2i+1}
                ull u0 = ((ulonglong2*)&gq)->x;
                ull u1 = ((ulonglong2*)&gq)->y;
                fma_x2(acc[2*i+0][0], u0, fa.x);
                fma_x2(acc[2*i+0][1], u0, fa.y);
                fma_x2(acc[2*i+0][2], u0, fb.x);
                fma_x2(acc[2*i+0][3], u0, fb.y);
                fma_x2(acc[2*i+1][0], u1, fa.x);
                fma_x2(acc[2*i+1][1], u1, fa.y);
                fma_x2(acc[2*i+1][2], u1, fb.x);
                fma_x2(acc[2*i+1][3], u1, fb.y);
            }
        }

        // packed epilogue: v2 = fma(-2, acc2, gn2 + nf2); scalar lanes bit-exact
        int base1 = f0 + lane * 4, base2 = f0 + 128 + lane * 4;
#pragma unroll
        for (int r = 0; r < 8; r++) {
            float gn = Gn[w * 8 + r];
            ull gn2 = pack2(gn, gn);
#pragma unroll
            for (int p = 0; p < 4; p++) {
                ull nfp = (p < 2) ? NsU[lane * 2 + p] : NsU[64 + lane * 2 + (p - 2)];
                ull sn2 = add_x2(gn2, nfp);
                ull v2 = fma_x2v(NEG2, acc[r][p], sn2);
                float v0 = __uint_as_float((unsigned)v2);
                float v1 = __uint_as_float((unsigned)(v2 >> 32));
                if (fminf(v0, v1) < bv[r][2]) {
                    int i0 = (p < 2) ? (base1 + 2 * p) : (base2 + 2 * (p - 2));
                    top3_ins(v0, i0,     bv[r], bi[r]);
                    top3_ins(v1, i0 + 1, bv[r], bi[r]);
                }
            }
        }
    }

    // per-goal warp merge: 3 rounds of u64 min + pop (keys unique: idx unique)
#pragma unroll
    for (int r = 0; r < 8; r++) {
        ull cand[3];
#pragma unroll
        for (int t = 0; t < 3; t++)
            cand[t] = ((ull)fkey(bv[r][t]) << 32) | (unsigned)bi[r][t];
        int p = 0;
#pragma unroll
        for (int t = 0; t < 3; t++) {
            ull cur = (p < 3) ? cand[p] : ~0ull;
            ull m = cur;
            for (int off = 16; off; off >>= 1) {
                ull o = __shfl_xor_sync(0xffffffffu, m, off);
                if (o < m) m = o;
            }
            if (cur == m) p++;
            if (lane == 0) {
                int g = g0 + w * 8 + r;
                int base = (g * NSPLIT + blockIdx.y) * 3 + t;
                g_candU[base] = (unsigned)(m >> 32);
                g_candI[base] = (int)(m & 0xffffffffu);
            }
        }
    }
}

// ---------------- merge split candidates + gather mean ----------------
__global__ void finalize_k(const float* __restrict__ Frow, int ngoals,
                           float* __restrict__ outp) {
    int w = threadIdx.x >> 5, lane = threadIdx.x & 31;
    int g = blockIdx.x * 8 + w;
    if (g >= ngoals) return;
    ull key = ~0ull;
    if (lane < NSPLIT * 3)
        key = ((ull)g_candU[g * NSPLIT * 3 + lane] << 32) |
              (unsigned)g_candI[g * NSPLIT * 3 + lane];
    int idxs[3];
#pragma unroll
    for (int t = 0; t < 3; t++) {
        ull m = key;
        for (int off = 16; off; off >>= 1) {
            ull o = __shfl_xor_sync(0xffffffffu, m, off);
            if (o < m) m = o;
        }
        if (key == m) key = ~0ull;
        idxs[t] = (int)(m & 0xffffffffu);
    }
    const float* r0 = Frow + (size_t)idxs[0] * KD;
    const float* r1 = Frow + (size_t)idxs[1] * KD;
    const float* r2 = Frow + (size_t)idxs[2] * KD;
#pragma unroll
    for (int d = lane; d < KD; d += 32)
        outp[(size_t)g * KD + d] = ((r0[d] + r1[d]) + r2[d]) / 3.0f;
}

// ---------------- orchestration ----------------
extern "C" void kernel_launch(void* const* d_in, const int* in_sizes, int n_in,
                              void* d_out, int out_size) {
    const float* x = (const float*)d_in[0];   // [4096, 64] fp32
    float* out = (float*)d_out;               // [12288, 64] fp32

    const int KNN_SMEM = KD * NB * 4 + KD * MB * 8 + NB * 4 + MB * 4;  // 99584
    cudaFuncSetAttribute(knn_k, cudaFuncAttributeMaxDynamicSharedMemorySize,
                         KNN_SMEM);

    // rows [0, 4096) = x
    cudaMemcpyAsync(out, x, (size_t)4096 * KD * sizeof(float),
                    cudaMemcpyDeviceToDevice);

    // ---- step 1 (launch order puts knn_k 4th so ncu profiles it) ----
    transpose_k<<<dim3(4096 / 32, 2), dim3(32, 32)>>>(x, 0);          // 1
    norms_k<<<4096 / 256, 256>>>(0);                                  // 2
    keys_k<<<NPTS / 512, 512>>>();                                    // 3 (indep)
    knn_k<<<dim3(4096 / MB, NSPLIT), 256, KNN_SMEM>>>(4096, 0);       // 4
    rank_k<<<dim3(NPTS / 256, 2, NPTS / SEG), 256>>>();               // 5 (indep)
    compose_k<<<NPTS / 512, 512>>>();                                 // 6
    finalize_k<<<4096 / 8, 256>>>(x, 4096, out + (size_t)4096 * KD);  // 7

    // ---- step 2: feats = out[0:8192], goals = feats[perm[:4096]] ----
    transpose_k<<<dim3(4096 / 32, 2), dim3(32, 32)>>>(out + (size_t)4096 * KD, 4096);
    norms_k<<<4096 / 256, 256>>>(4096);
    knn_k<<<dim3(4096 / MB, NSPLIT), 256, KNN_SMEM>>>(8192, 1);
    finalize_k<<<4096 / 8, 256>>>(out, 4096, out + (size_t)8192 * KD);
}

// round 8
// speedup vs baseline: 1.3030x; 1.3030x over previous
#include <cuda_runtime.h>
#include <cuda_bf16.h>
#include <cstdint>

typedef unsigned long long ull;

#define KD 64      // feature dimension
#define LD 8192    // leading dim of transposed feature matrix
#define MB 64      // goals per block (8 warps x 8 goals)
#define NB 128     // features per tile (lane owns 4)
#define NSPLIT 4   // feature-dim split per step -> 256 blocks = 1 wave @ occ 2
#define NPTS 8192

// ---------------- scratch (__device__ globals; no allocation) ----------------
__device__ float g_FT[KD * LD];          // transposed features [64][8192]
__device__ float g_norms[LD];            // |f|^2
__device__ unsigned g_candU[4096 * NSPLIT * 3];
__device__ int      g_candI[4096 * NSPLIT * 3];
__device__ ull g_kA[NPTS], g_kB[NPTS];   // round-1/2 sort keys (bits<<32|pos)
__device__ int g_rA[NPTS], g_rB[NPTS];   // ranks
__device__ int g_perm[NPTS];             // final permutation (rand_inds = first 4096)

// ---------------- threefry2x32 (exact JAX) ----------------
__device__ __forceinline__ void tf2x32(unsigned k0, unsigned k1,
                                       unsigned c0, unsigned c1,
                                       unsigned &o0, unsigned &o1) {
    unsigned ks2 = k0 ^ k1 ^ 0x1BD11BDAu;
    unsigned x0 = c0 + k0, x1 = c1 + k1;
#define TF_RND(r) { x0 += x1; x1 = (x1 << (r)) | (x1 >> (32 - (r))); x1 ^= x0; }
    TF_RND(13) TF_RND(15) TF_RND(26) TF_RND(6)   x0 += k1;  x1 += ks2 + 1u;
    TF_RND(17) TF_RND(29) TF_RND(16) TF_RND(24)  x0 += ks2; x1 += k0 + 2u;
    TF_RND(13) TF_RND(15) TF_RND(26) TF_RND(6)   x0 += k0;  x1 += k1 + 3u;
    TF_RND(17) TF_RND(29) TF_RND(16) TF_RND(24)  x0 += k1;  x1 += ks2 + 4u;
    TF_RND(13) TF_RND(15) TF_RND(26) TF_RND(6)   x0 += ks2; x1 += k0 + 5u;
#undef TF_RND
    o0 = x0; o1 = x1;
}

// partitionable threefry: round r: key,subkey = split(key), counters (0,0),(0,1)
__device__ __forceinline__ void subkeys(unsigned &s10, unsigned &s11,
                                        unsigned &s20, unsigned &s21) {
    unsigned n0, n1;
    tf2x32(0u, 42u, 0u, 0u, n0, n1);
    tf2x32(0u, 42u, 0u, 1u, s10, s11);
    tf2x32(n0, n1, 0u, 1u, s20, s21);
}

// bits[i] = y0 ^ y1 with counter (0, i); stable-sort key = (bits<<32) | i.
// Also zeroes the rank arrays (graph replays must be deterministic).
__global__ void keys_k() {
    int i = blockIdx.x * blockDim.x + threadIdx.x;
    if (i >= NPTS) return;
    unsigned s10, s11, s20, s21;
    subkeys(s10, s11, s20, s21);
    unsigned lo, hi;
    tf2x32(s10, s11, 0u, (unsigned)i, lo, hi);
    g_kA[i] = ((ull)(lo ^ hi) << 32) | (unsigned)i;
    tf2x32(s20, s21, 0u, (unsigned)i, lo, hi);
    g_kB[i] = ((ull)(lo ^ hi) << 32) | (unsigned)i;
    g_rA[i] = 0; g_rB[i] = 0;
}

// rank[i] = #{j : key_j < key_i}, segmented over j, REDG-accumulated.
#define SEG 2048
__global__ __launch_bounds__(256) void rank_k() {
    __shared__ ull tile[SEG];
    const ull* K = blockIdx.y ? g_kB : g_kA;
    int* R = blockIdx.y ? g_rB : g_rA;
    int i = blockIdx.x * 256 + threadIdx.x;
    int base = blockIdx.z * SEG;
    ull my = K[i];
    for (int j = threadIdx.x; j < SEG; j += 256) tile[j] = K[base + j];
    __syncthreads();
    int cnt = 0;
#pragma unroll 8
    for (int j = 0; j < SEG; j++) cnt += (tile[j] < my);
    atomicAdd(&R[i], cnt);
}

// perm[rB[rA[i]]] = i
__global__ void compose_k() {
    int i = blockIdx.x * blockDim.x + threadIdx.x;
    if (i >= NPTS) return;
    g_perm[g_rB[g_rA[i]]] = i;
}

// ---------------- transpose rows[n][64] -> g_FT[64][foff+...] ----------------
__global__ void transpose_k(const float* __restrict__ in, int foff) {
    __shared__ float t[32][33];
    int f0 = blockIdx.x * 32, d0 = blockIdx.y * 32;
    int tx = threadIdx.x, ty = threadIdx.y;
    t[ty][tx] = in[(size_t)(f0 + ty) * KD + d0 + tx];
    __syncthreads();
    g_FT[(size_t)(d0 + ty) * LD + foff + f0 + tx] = t[tx][ty];
}

// ---------------- norms: |f|^2 for f in [foff, foff+n) ----------------
__global__ void norms_k(int foff) {
    int f = foff + blockIdx.x * blockDim.x + threadIdx.x;
    float s = 0.f;
#pragma unroll
    for (int k = 0; k < KD; k++) {
        float v = g_FT[(size_t)k * LD + f];
        s = __fadd_rn(s, __fmul_rn(v, v));
    }
    g_norms[f] = s;
}

// ---------------- ordered-float key for tie-break-by-lower-index min ----------------
__device__ __forceinline__ unsigned fkey(float f) {
    unsigned u = __float_as_uint(f);
    return (u & 0x80000000u) ? ~u : (u | 0x80000000u);
}

__device__ __forceinline__ void fma_x2(ull &acc, ull a, ull b) {
    asm("fma.rn.f32x2 %0, %1, %2, %3;" : "=l"(acc) : "l"(a), "l"(b), "l"(acc));
}
__device__ __forceinline__ ull add_x2(ull a, ull b) {
    ull r; asm("add.rn.f32x2 %0, %1, %2;" : "=l"(r) : "l"(a), "l"(b)); return r;
}
__device__ __forceinline__ ull fma_x2v(ull a, ull b, ull c) {
    ull r; asm("fma.rn.f32x2 %0, %1, %2, %3;" : "=l"(r) : "l"(a), "l"(b), "l"(c));
    return r;
}
__device__ __forceinline__ ull pack2(float lo, float hi) {
    ull r; asm("mov.b64 %0, {%1, %2};" : "=l"(r) : "f"(lo), "f"(hi)); return r;
}

__device__ __forceinline__ unsigned int smem_u32(const void* p) {
    unsigned int a;
    asm("{ .reg .u64 t; cvta.to.shared.u64 t, %1; cvt.u32.u64 %0, t; }"
        : "=r"(a) : "l"(p));
    return a;
}
__device__ __forceinline__ void cp_async16(unsigned int s, const void* g) {
    asm volatile("cp.async.cg.shared.global [%0], [%1], 16;" :: "r"(s), "l"(g));
}
__device__ __forceinline__ void cp_commit() {
    asm volatile("cp.async.commit_group;" ::: "memory");
}
__device__ __forceinline__ void cp_wait0() {
    asm volatile("cp.async.wait_group 0;" ::: "memory");
}

__device__ __forceinline__ void top3_ins(float v, int idx, float* bv, int* bi) {
    if (v < bv[2]) {
        if (v < bv[1]) {
            bv[2] = bv[1]; bi[2] = bi[1];
            if (v < bv[0]) {
                bv[1] = bv[0]; bi[1] = bi[0];
                bv[0] = v; bi[0] = idx;
            } else { bv[1] = v; bi[1] = idx; }
        } else { bv[2] = v; bi[2] = idx; }
    }
}

// ---------------- KNN top-3: f32x2 8x4 tile, occ 2, cp.async double buffer ----------
// grid = (4096/MB, NSPLIT), block = 256 (8 warps), 2 blocks/SM.
// Warp w owns goals [w*8, w*8+8); lane owns feats lane*4..+3. Goals pair-duplicated.
// Per warp-k: 1 LDS.128 feats + 4 LDS.128bc goals (8 wf) + 16 FFMA2.
// Feature tiles are double-buffered via cp.async (copy t+1 overlaps compute t).
__global__ __launch_bounds__(256, 2) void knn_k(int nfeat, int usePerm) {
    extern __shared__ float sm[];
    float* Fs = sm;                        // [2][64][128]  feats, double-buffered
    float* Gp = Fs + 2 * KD * NB;          // [64][64*2]    pair-duplicated goals
    float* Ns = Gp + KD * MB * 2;          // [2][128]      feat norms, dbuf
    float* Gn = Ns + 2 * NB;               // [64]
    float4* Gp4 = (float4*)Gp;             // row k: 32 entries ({g,g,g',g'})

    int tid = threadIdx.x;
    int lane = tid & 31, w = tid >> 5;
    int g0 = blockIdx.x * MB;
    int part = nfeat / NSPLIT;
    int fBeg = blockIdx.y * part;
    int T = part / NB;

    unsigned int sF = smem_u32(Fs), sN = smem_u32(Ns);

    for (int i = tid; i < KD * MB; i += 256) {
        int k = i >> 6, j = i & 63;
        int src = usePerm ? g_perm[g0 + j] : (g0 + j);
        float v = g_FT[(size_t)k * LD + src];
        ((float2*)Gp)[k * MB + j] = make_float2(v, v);
    }
    if (tid < MB) {
        int src = usePerm ? g_perm[g0 + tid] : (g0 + tid);
        Gn[tid] = g_norms[src];
    }

    // issue copy of tile 0 into buffer 0
    {
        int f0 = fBeg;
#pragma unroll
        for (int j = 0; j < 8; j++) {
            int i = tid + 256 * j;
            int k = i >> 5, c = i & 31;
            cp_async16(sF + (unsigned)(k * 32 + c) * 16,
                       &g_FT[(size_t)k * LD + f0 + 4 * c]);
        }
        if (tid < 32)
            cp_async16(sN + tid * 16, &g_norms[f0 + tid * 4]);
        cp_commit();
    }

    float bv[8][3]; int bi[8][3];
#pragma unroll
    for (int r = 0; r < 8; r++)
#pragma unroll
        for (int t = 0; t < 3; t++) { bv[r][t] = 3.402823466e38f; bi[r][t] = 0; }

    const ull NEG2 = ((ull)0xC0000000u << 32) | 0xC0000000u;   // {-2.f, -2.f}

    for (int t = 0; t < T; t++) {
        cp_wait0();
        __syncthreads();   // tile t landed everywhere; all warps done with buf t&1

        // overlap: issue copy of tile t+1 into the other buffer
        if (t + 1 < T) {
            int f1 = fBeg + (t + 1) * NB;
            unsigned int bF = sF + (unsigned)((t + 1) & 1) * KD * NB * 4;
            unsigned int bN = sN + (unsigned)((t + 1) & 1) * NB * 4;
#pragma unroll
            for (int j = 0; j < 8; j++) {
                int i = tid + 256 * j;
                int k = i >> 5, c = i & 31;
                cp_async16(bF + (unsigned)(k * 32 + c) * 16,
                           &g_FT[(size_t)k * LD + f1 + 4 * c]);
            }
            if (tid < 32)
                cp_async16(bN + tid * 16, &g_norms[f1 + tid * 4]);
            cp_commit();
        }

        const ulonglong2* FsV = (const ulonglong2*)(Fs + (t & 1) * KD * NB);
        const ull* NsU = (const ull*)(Ns + (t & 1) * NB);
        int f0 = fBeg + t * NB;

        ull acc[8][2];
#pragma unroll
        for (int r = 0; r < 8; r++) { acc[r][0] = 0ull; acc[r][1] = 0ull; }

#pragma unroll 16
        for (int k = 0; k < KD; k++) {
            ulonglong2 fq = FsV[k * 32 + lane];        // feats lane*4 .. +3
#pragma unroll
            for (int i = 0; i < 4; i++) {
                float4 gq = Gp4[k * 32 + w * 4 + i];   // {g2i,g2i, g2i+1,g2i+1}
                ull u0 = ((ulonglong2*)&gq)->x;
                ull u1 = ((ulonglong2*)&gq)->y;
                fma_x2(acc[2*i+0][0], u0, fq.x);
                fma_x2(acc[2*i+0][1], u0, fq.y);
                fma_x2(acc[2*i+1][0], u1, fq.x);
                fma_x2(acc[2*i+1][1], u1, fq.y);
            }
        }

        // packed epilogue: v2 = fma(-2, acc2, gn2 + nf2); scalar lanes bit-exact
        int base = f0 + lane * 4;
        ull nf0 = NsU[lane * 2], nf1 = NsU[lane * 2 + 1];
#pragma unroll
        for (int r = 0; r < 8; r++) {
            float gn = Gn[w * 8 + r];
            ull gn2 = pack2(gn, gn);
#pragma unroll
            for (int p = 0; p < 2; p++) {
                ull sn2 = add_x2(gn2, p ? nf1 : nf0);
                ull v2 = fma_x2v(NEG2, acc[r][p], sn2);
                float v0 = __uint_as_float((unsigned)v2);
                float v1 = __uint_as_float((unsigned)(v2 >> 32));
                if (fminf(v0, v1) < bv[r][2]) {
                    top3_ins(v0, base + 2 * p,     bv[r], bi[r]);
                    top3_ins(v1, base + 2 * p + 1, bv[r], bi[r]);
                }
            }
        }
    }

    // per-goal warp merge: 3 rounds of u64 min + pop (keys unique: idx unique)
#pragma unroll
    for (int r = 0; r < 8; r++) {
        ull cand[3];
#pragma unroll
        for (int t = 0; t < 3; t++)
            cand[t] = ((ull)fkey(bv[r][t]) << 32) | (unsigned)bi[r][t];
        int p = 0;
#pragma unroll
        for (int t = 0; t < 3; t++) {
            ull cur = (p < 3) ? cand[p] : ~0ull;
            ull m = cur;
            for (int off = 16; off; off >>= 1) {
                ull o = __shfl_xor_sync(0xffffffffu, m, off);
                if (o < m) m = o;
            }
            if (cur == m) p++;
            if (lane == 0) {
                int g = g0 + w * 8 + r;
                int base2 = (g * NSPLIT + blockIdx.y) * 3 + t;
                g_candU[base2] = (unsigned)(m >> 32);
                g_candI[base2] = (int)(m & 0xffffffffu);
            }
        }
    }
}

// ---------------- merge split candidates + gather mean ----------------
__global__ void finalize_k(const float* __restrict__ Frow, int ngoals,
                           float* __restrict__ outp) {
    int w = threadIdx.x >> 5, lane = threadIdx.x & 31;
    int g = blockIdx.x * 8 + w;
    if (g >= ngoals) return;
    ull key = ~0ull;
    if (lane < NSPLIT * 3)
        key = ((ull)g_candU[g * NSPLIT * 3 + lane] << 32) |
              (unsigned)g_candI[g * NSPLIT * 3 + lane];
    int idxs[3];
#pragma unroll
    for (int t = 0; t < 3; t++) {
        ull m = key;
        for (int off = 16; off; off >>= 1) {
            ull o = __shfl_xor_sync(0xffffffffu, m, off);
            if (o < m) m = o;
        }
        if (key == m) key = ~0ull;
        idxs[t] = (int)(m & 0xffffffffu);
    }
    const float* r0 = Frow + (size_t)idxs[0] * KD;
    const float* r1 = Frow + (size_t)idxs[1] * KD;
    const float* r2 = Frow + (size_t)idxs[2] * KD;
#pragma unroll
    for (int d = lane; d < KD; d += 32)
        outp[(size_t)g * KD + d] = ((r0[d] + r1[d]) + r2[d]) / 3.0f;
}

// ---------------- orchestration ----------------
extern "C" void kernel_launch(void* const* d_in, const int* in_sizes, int n_in,
                              void* d_out, int out_size) {
    const float* x = (const float*)d_in[0];   // [4096, 64] fp32
    float* out = (float*)d_out;               // [12288, 64] fp32

    const int KNN_SMEM = 2 * KD * NB * 4 + KD * MB * 8 + 2 * NB * 4 + MB * 4; // 99584
    cudaFuncSetAttribute(knn_k, cudaFuncAttributeMaxDynamicSharedMemorySize,
                         KNN_SMEM);

    // rows [0, 4096) = x
    cudaMemcpyAsync(out, x, (size_t)4096 * KD * sizeof(float),
                    cudaMemcpyDeviceToDevice);

    // ---- step 1 (launch order puts knn_k 4th so ncu profiles it) ----
    transpose_k<<<dim3(4096 / 32, 2), dim3(32, 32)>>>(x, 0);          // 1
    norms_k<<<4096 / 256, 256>>>(0);                                  // 2
    keys_k<<<NPTS / 512, 512>>>();                                    // 3 (indep)
    knn_k<<<dim3(4096 / MB, NSPLIT), 256, KNN_SMEM>>>(4096, 0);       // 4
    rank_k<<<dim3(NPTS / 256, 2, NPTS / SEG), 256>>>();               // 5 (indep)
    compose_k<<<NPTS / 512, 512>>>();                                 // 6
    finalize_k<<<4096 / 8, 256>>>(x, 4096, out + (size_t)4096 * KD);  // 7

    // ---- step 2: feats = out[0:8192], goals = feats[perm[:4096]] ----
    transpose_k<<<dim3(4096 / 32, 2), dim3(32, 32)>>>(out + (size_t)4096 * KD, 4096);
    norms_k<<<4096 / 256, 256>>>(4096);
    knn_k<<<dim3(4096 / MB, NSPLIT), 256, KNN_SMEM>>>(8192, 1);
    finalize_k<<<4096 / 8, 256>>>(out, 4096, out + (size_t)8192 * KD);
}